// round 11
// baseline (speedup 1.0000x reference)
#include <cuda_runtime.h>
#include <cuda_bf16.h>
#include <stdint.h>
#include <cstdint>
#include <math.h>

// Problem constants
#define SQ   2048
#define DM   1024
#define NH   16
#define DH   64
#define BT   2
#define NTOK (BT*SQ)      // 4096
#define DMLP 4096

typedef __nv_bfloat16 bf16;

// ---------------- scratch (device globals; no allocations allowed) ----------
__device__ float g_q   [NTOK*DM];      // [B,H,S,DH] fp32
__device__ float g_k   [NTOK*DM];
__device__ float g_v   [NTOK*DM];
__device__ float g_rmid[NTOK*DM];

__device__ bf16 g_xln_h[NTOK*DM],  g_xln_l[NTOK*DM];
__device__ bf16 g_z_h  [NTOK*DM],  g_z_l  [NTOK*DM];
__device__ bf16 g_h2_h [NTOK*DM],  g_h2_l [NTOK*DM];
__device__ bf16 g_act_h[NTOK*DMLP],g_act_l[NTOK*DMLP];

__device__ bf16 g_wq_h [DM*DM],    g_wq_l [DM*DM];     // repacked [d, h*64+k]
__device__ bf16 g_wk_h [DM*DM],    g_wk_l [DM*DM];
__device__ bf16 g_wv_h [DM*DM],    g_wv_l [DM*DM];
__device__ bf16 g_wo_h [DM*DM],    g_wo_l [DM*DM];
__device__ bf16 g_win_h[DM*DMLP],  g_win_l[DM*DMLP];
__device__ bf16 g_wout_h[DMLP*DM], g_wout_l[DMLP*DM];

__device__ __forceinline__ void split_val(float f, bf16& h, bf16& l) {
    h = __float2bfloat16(f);
    l = __float2bfloat16(f - __bfloat162float(h));
}

// ---------------- weight repack+split: [h,d,k] -> [d, h*64+k] ---------------
__global__ void repack_kernel(const float* __restrict__ wq,
                              const float* __restrict__ wk,
                              const float* __restrict__ wv) {
    int idx = blockIdx.x * 256 + threadIdx.x;
    int d  = idx >> 10;
    int n  = idx & 1023;
    int h  = n >> 6;
    int kk = n & 63;
    int src = h * (DM * DH) + d * DH + kk;
    split_val(wq[src], g_wq_h[idx], g_wq_l[idx]);
    split_val(wk[src], g_wk_h[idx], g_wk_l[idx]);
    split_val(wv[src], g_wv_h[idx], g_wv_l[idx]);
}

// ---------------- generic fp32 -> bf16 hi/lo split ---------------------------
__global__ void split_kernel(const float* __restrict__ src,
                             bf16* __restrict__ hi, bf16* __restrict__ lo) {
    int i = (blockIdx.x * 256 + threadIdx.x) * 4;
    float4 v = *(const float4*)(src + i);
    bf16 h0,l0,h1,l1,h2,l2,h3,l3;
    split_val(v.x,h0,l0); split_val(v.y,h1,l1);
    split_val(v.z,h2,l2); split_val(v.w,h3,l3);
    __nv_bfloat162 hh0 = {h0,h1}, hh1 = {h2,h3};
    __nv_bfloat162 ll0 = {l0,l1}, ll1 = {l2,l3};
    *(__nv_bfloat162*)(hi + i)     = hh0;
    *(__nv_bfloat162*)(hi + i + 2) = hh1;
    *(__nv_bfloat162*)(lo + i)     = ll0;
    *(__nv_bfloat162*)(lo + i + 2) = ll1;
}

// ---------------- layernorm -> bf16 hi/lo ------------------------------------
__global__ void ln_kernel(const float* __restrict__ x, const float* __restrict__ w,
                          const float* __restrict__ b,
                          bf16* __restrict__ yh, bf16* __restrict__ yl) {
    int row = blockIdx.x;
    int t = threadIdx.x;
    const float4 xv = *(const float4*)(x + (size_t)row * DM + t * 4);
    float s  = xv.x + xv.y + xv.z + xv.w;
    float ss = xv.x*xv.x + xv.y*xv.y + xv.z*xv.z + xv.w*xv.w;
    #pragma unroll
    for (int o = 16; o; o >>= 1) {
        s  += __shfl_xor_sync(0xffffffffu, s,  o);
        ss += __shfl_xor_sync(0xffffffffu, ss, o);
    }
    __shared__ float sb[8], sb2[8];
    int wid = t >> 5, lane = t & 31;
    if (lane == 0) { sb[wid] = s; sb2[wid] = ss; }
    __syncthreads();
    if (wid == 0) {
        s  = sb[lane & 7];
        ss = sb2[lane & 7];
        #pragma unroll
        for (int o = 4; o; o >>= 1) {
            s  += __shfl_xor_sync(0xffffffffu, s,  o);
            ss += __shfl_xor_sync(0xffffffffu, ss, o);
        }
        if (lane == 0) { sb[0] = s; sb2[0] = ss; }
    }
    __syncthreads();
    float mean = sb[0] * (1.0f / DM);
    float var  = sb2[0] * (1.0f / DM) - mean * mean;
    float rstd = rsqrtf(var + 1e-5f);
    float4 wv4 = *(const float4*)(w + t * 4);
    float4 bv4 = *(const float4*)(b + t * 4);
    float o0 = (xv.x - mean) * rstd * wv4.x + bv4.x;
    float o1 = (xv.y - mean) * rstd * wv4.y + bv4.y;
    float o2 = (xv.z - mean) * rstd * wv4.z + bv4.z;
    float o3 = (xv.w - mean) * rstd * wv4.w + bv4.w;
    bf16 h0,l0,h1,l1,h2,l2,h3,l3;
    split_val(o0,h0,l0); split_val(o1,h1,l1);
    split_val(o2,h2,l2); split_val(o3,h3,l3);
    size_t base = (size_t)row * DM + t * 4;
    __nv_bfloat162 hh0 = {h0,h1}, hh1 = {h2,h3};
    __nv_bfloat162 ll0 = {l0,l1}, ll1 = {l2,l3};
    *(__nv_bfloat162*)(yh + base)     = hh0;
    *(__nv_bfloat162*)(yh + base + 2) = hh1;
    *(__nv_bfloat162*)(yl + base)     = ll0;
    *(__nv_bfloat162*)(yl + base + 2) = ll1;
}

// ---------------- mma helpers ------------------------------------------------
__device__ __forceinline__ uint32_t smem_u32(const void* p) {
    return (uint32_t)__cvta_generic_to_shared(p);
}

__device__ __forceinline__ void cp16(uint32_t dst, const void* src) {
    asm volatile("cp.async.cg.shared.global [%0], [%1], 16;"
                 :: "r"(dst), "l"((unsigned long long)__cvta_generic_to_global(src)));
}
#define CP_COMMIT() asm volatile("cp.async.commit_group;")
#define CP_WAIT1()  asm volatile("cp.async.wait_group 1;")
#define CP_WAIT0()  asm volatile("cp.async.wait_group 0;")

#define LDSM_X4(r0,r1,r2,r3,addr) \
    asm volatile("ldmatrix.sync.aligned.m8n8.x4.shared.b16 {%0,%1,%2,%3}, [%4];" \
        : "=r"(r0),"=r"(r1),"=r"(r2),"=r"(r3) : "r"(addr))

#define LDSM_X4_T(r0,r1,r2,r3,addr) \
    asm volatile("ldmatrix.sync.aligned.m8n8.x4.trans.shared.b16 {%0,%1,%2,%3}, [%4];" \
        : "=r"(r0),"=r"(r1),"=r"(r2),"=r"(r3) : "r"(addr))

#define MMA16816(c, a0,a1,a2,a3, b0,b1) \
    asm volatile("mma.sync.aligned.m16n8k16.row.col.f32.bf16.bf16.f32 " \
        "{%0,%1,%2,%3}, {%4,%5,%6,%7}, {%8,%9}, {%0,%1,%2,%3};" \
        : "+f"(c[0]),"+f"(c[1]),"+f"(c[2]),"+f"(c[3]) \
        : "r"(a0),"r"(a1),"r"(a2),"r"(a3), "r"(b0),"r"(b1))

__device__ __forceinline__ uint32_t pack_bf2(float a, float b) {
    __nv_bfloat162 t = __floats2bfloat162_rn(a, b);
    return *reinterpret_cast<uint32_t*>(&t);
}

// ---------------- tensor-core GEMM: pre-split bf16 hi/lo, cp.async 2-stage ---
// C = A*B (+bias/epilogue). A: hi/lo [M,K]; B: hi/lo [K,N]. 3-pass hi/lo MMA.
// CTA tile 128x128x32, 8 warps (2x4). MODE: 1=QKV scatter, 2=+R, 3=relu->hi/lo.
#define APAD 40
#define BPAD 136
#define A_SZ (128*APAD)              // elems per A buffer per stage
#define B_SZ (32*BPAD)
#define STAGE_E (2*A_SZ + 2*B_SZ)    // 18944 elems
#define STAGE_B (STAGE_E*2)          // 37888 bytes
#define HGEMM_SMEM (2*STAGE_B)       // 75776 bytes

template <int MODE>
__global__ __launch_bounds__(256, 2)
void hgemm_kernel(const bf16* __restrict__ Ah, const bf16* __restrict__ Al,
                  const bf16* __restrict__ Bh, const bf16* __restrict__ Bl,
                  const float* __restrict__ bias, const float* __restrict__ R,
                  float* __restrict__ C, bf16* __restrict__ Ch, bf16* __restrict__ Cl,
                  int M, int N, int K) {
    extern __shared__ __align__(16) bf16 smem_buf[];
    uint32_t s_base = smem_u32(smem_buf);

    int tid = threadIdx.x;
    int lane = tid & 31;
    int warp = tid >> 5;
    int wm = warp >> 2;
    int wn = warp & 3;
    int m0 = blockIdx.y * 128, n0 = blockIdx.x * 128;

    float acc[4][4][4];
    #pragma unroll
    for (int i = 0; i < 4; i++)
        #pragma unroll
        for (int j = 0; j < 4; j++)
            #pragma unroll
            for (int c = 0; c < 4; c++) acc[i][j][c] = 0.0f;

    // fragment smem base addresses (stage 0)
    uint32_t a_hi0 = s_base + (uint32_t)(((wm*64 + (lane & 15)) * APAD + (lane >> 4) * 8) * 2);
    uint32_t a_lo0 = a_hi0 + A_SZ * 2;
    uint32_t b_hi0 = s_base + (uint32_t)((2*A_SZ + (lane & 15) * BPAD + wn*32 + (lane >> 4) * 8) * 2);
    uint32_t b_lo0 = b_hi0 + B_SZ * 2;

    // staging: 512 16B-chunks for A (hi+lo each), 512 for B; 2 chunks/thread each
    auto load_stage = [&](int k0, int st) {
        uint32_t sb = s_base + (uint32_t)(st * STAGE_B);
        #pragma unroll
        for (int h = 0; h < 2; h++) {
            int idx = tid + h * 256;
            int r  = idx >> 2,  c8  = (idx & 3)  * 8;   // A: 128 rows x 4 chunks
            const bf16* sAh = Ah + (size_t)(m0 + r) * K + k0 + c8;
            const bf16* sAl = Al + (size_t)(m0 + r) * K + k0 + c8;
            cp16(sb + (uint32_t)((r * APAD + c8) * 2), sAh);
            cp16(sb + (uint32_t)((A_SZ + r * APAD + c8) * 2), sAl);
            int rb = idx >> 4, cb8 = (idx & 15) * 8;    // B: 32 rows x 16 chunks
            const bf16* sBh = Bh + (size_t)(k0 + rb) * N + n0 + cb8;
            const bf16* sBl = Bl + (size_t)(k0 + rb) * N + n0 + cb8;
            cp16(sb + (uint32_t)((2*A_SZ + rb * BPAD + cb8) * 2), sBh);
            cp16(sb + (uint32_t)((2*A_SZ + B_SZ + rb * BPAD + cb8) * 2), sBl);
        }
    };

    int nk = K >> 5;
    load_stage(0, 0);
    CP_COMMIT();

    for (int kt = 0; kt < nk; kt++) {
        int st = kt & 1;
        if (kt + 1 < nk) {
            load_stage((kt + 1) * 32, st ^ 1);
            CP_COMMIT();
            CP_WAIT1();
        } else {
            CP_WAIT0();
        }
        __syncthreads();

        uint32_t so = (uint32_t)(st * STAGE_B);
        #pragma unroll
        for (int ks = 0; ks < 2; ks++) {
            uint32_t bh[8], bl[8];
            {
                uint32_t off = so + (uint32_t)(ks * 16 * BPAD * 2);
                LDSM_X4_T(bh[0], bh[1], bh[2], bh[3], b_hi0 + off);
                LDSM_X4_T(bh[4], bh[5], bh[6], bh[7], b_hi0 + off + 16 * 2);
                LDSM_X4_T(bl[0], bl[1], bl[2], bl[3], b_lo0 + off);
                LDSM_X4_T(bl[4], bl[5], bl[6], bl[7], b_lo0 + off + 16 * 2);
            }
            #pragma unroll
            for (int i = 0; i < 4; i++) {
                uint32_t ah0, ah1, ah2, ah3, al0, al1, al2, al3;
                uint32_t aoff = so + (uint32_t)((i * 16 * APAD + ks * 16) * 2);
                LDSM_X4(ah0, ah1, ah2, ah3, a_hi0 + aoff);
                LDSM_X4(al0, al1, al2, al3, a_lo0 + aoff);
                #pragma unroll
                for (int j = 0; j < 4; j++) {
                    MMA16816(acc[i][j], ah0, ah1, ah2, ah3, bh[2*j], bh[2*j+1]);
                    MMA16816(acc[i][j], ah0, ah1, ah2, ah3, bl[2*j], bl[2*j+1]);
                    MMA16816(acc[i][j], al0, al1, al2, al3, bh[2*j], bh[2*j+1]);
                }
            }
        }
        __syncthreads();
    }

    // ---- epilogue ----
    int gid = lane >> 2;
    int tid4 = lane & 3;
    #pragma unroll
    for (int i = 0; i < 4; i++) {
        #pragma unroll
        for (int j = 0; j < 4; j++) {
            #pragma unroll
            for (int c = 0; c < 4; c++) {
                int m = m0 + wm * 64 + i * 16 + gid + (c >> 1) * 8;
                int n = n0 + wn * 32 + j * 8 + tid4 * 2 + (c & 1);
                float val = acc[i][j][c] + bias[n];
                if (MODE == 1) {
                    int bb = m >> 11;
                    int s  = m & (SQ - 1);
                    int h  = n >> 6;
                    int dk = n & 63;
                    C[(((size_t)(bb * NH + h)) * SQ + s) * DH + dk] = val;
                } else if (MODE == 2) {
                    C[(size_t)m * N + n] = val + R[(size_t)m * N + n];
                } else {  // MODE 3: relu -> bf16 hi/lo
                    val = fmaxf(val, 0.0f);
                    bf16 h, l;
                    split_val(val, h, l);
                    Ch[(size_t)m * N + n] = h;
                    Cl[(size_t)m * N + n] = l;
                }
            }
        }
    }
}

// ---------------- tensor-core flash attention --------------------------------
// q,k,v: [B,H,S,DH] fp32. Out z: hi/lo bf16 [tok, h*64+dh].
#define FBM 128
#define FBN 64
#define FPITCH 72

__global__ __launch_bounds__(256, 1)
void flashmma_kernel(const float* __restrict__ q, const float* __restrict__ k,
                     const float* __restrict__ v,
                     bf16* __restrict__ zh, bf16* __restrict__ zl) {
    extern __shared__ bf16 fsm[];
    bf16* Qh = fsm;                       // [128][72]
    bf16* Ql = Qh + FBM * FPITCH;
    bf16* Kh = Ql + FBM * FPITCH;         // [64][72]
    bf16* Kl = Kh + FBN * FPITCH;
    bf16* Vh = Kl + FBN * FPITCH;         // [64][72]
    bf16* Vl = Vh + FBN * FPITCH;

    int qt = blockIdx.x, bh = blockIdx.y;
    int bb = bh >> 4, hh = bh & 15;
    int tid = threadIdx.x, lane = tid & 31, w = tid >> 5;
    int gid = lane >> 2, qd = lane & 3;

    const float* qbase = q + ((size_t)bh * SQ + (size_t)qt * FBM) * DH;
    const float* kbase = k + (size_t)bh * SQ * DH;
    const float* vbase = v + (size_t)bh * SQ * DH;

    #pragma unroll
    for (int j = 0; j < 8; j++) {
        int idx = tid + j * 256;
        int r = idx >> 4, c = (idx & 15) * 4;
        float4 t4 = *(const float4*)(qbase + (size_t)r * DH + c);
        float f[4] = {t4.x, t4.y, t4.z, t4.w};
        #pragma unroll
        for (int e = 0; e < 4; e++)
            split_val(f[e], Qh[r * FPITCH + c + e], Ql[r * FPITCH + c + e]);
    }
    __syncthreads();

    uint32_t qh[4][4], ql[4][4];
    #pragma unroll
    for (int kc = 0; kc < 4; kc++) {
        uint32_t a1 = smem_u32(&Qh[(w * 16 + (lane & 15)) * FPITCH + kc * 16 + (lane >> 4) * 8]);
        LDSM_X4(qh[kc][0], qh[kc][1], qh[kc][2], qh[kc][3], a1);
        uint32_t a2 = smem_u32(&Ql[(w * 16 + (lane & 15)) * FPITCH + kc * 16 + (lane >> 4) * 8]);
        LDSM_X4(ql[kc][0], ql[kc][1], ql[kc][2], ql[kc][3], a2);
    }

    float o[8][4];
    #pragma unroll
    for (int j = 0; j < 8; j++)
        #pragma unroll
        for (int c = 0; c < 4; c++) o[j][c] = 0.0f;
    float mi0 = -1e30f, mi1 = -1e30f, li0 = 0.0f, li1 = 0.0f;

    int row0g = qt * FBM + w * 16 + gid;
    int row1g = row0g + 8;

    int nkt = 2 * qt + 2;
    for (int kt = 0; kt < nkt; kt++) {
        __syncthreads();
        #pragma unroll
        for (int j = 0; j < 4; j++) {
            int idx = tid + j * 256;
            int r = idx >> 4, c = (idx & 15) * 4;
            float4 t4 = *(const float4*)(kbase + ((size_t)kt * FBN + r) * DH + c);
            float f[4] = {t4.x, t4.y, t4.z, t4.w};
            #pragma unroll
            for (int e = 0; e < 4; e++)
                split_val(f[e], Kh[r * FPITCH + c + e], Kl[r * FPITCH + c + e]);
            float4 u4 = *(const float4*)(vbase + ((size_t)kt * FBN + r) * DH + c);
            float g[4] = {u4.x, u4.y, u4.z, u4.w};
            #pragma unroll
            for (int e = 0; e < 4; e++)
                split_val(g[e], Vh[r * FPITCH + c + e], Vl[r * FPITCH + c + e]);
        }
        __syncthreads();

        float s[8][4];
        #pragma unroll
        for (int j = 0; j < 8; j++)
            #pragma unroll
            for (int c = 0; c < 4; c++) s[j][c] = 0.0f;

        #pragma unroll
        for (int kc = 0; kc < 4; kc++) {
            #pragma unroll
            for (int jj = 0; jj < 4; jj++) {
                uint32_t addr_h = smem_u32(&Kh[((jj * 2 + (lane >> 4)) * 8 + (lane & 7)) * FPITCH
                                               + kc * 16 + ((lane >> 3) & 1) * 8]);
                uint32_t addr_l = smem_u32(&Kl[((jj * 2 + (lane >> 4)) * 8 + (lane & 7)) * FPITCH
                                               + kc * 16 + ((lane >> 3) & 1) * 8]);
                uint32_t kh0, kh1, kh2, kh3, kl0, kl1, kl2, kl3;
                LDSM_X4(kh0, kh1, kh2, kh3, addr_h);
                LDSM_X4(kl0, kl1, kl2, kl3, addr_l);
                MMA16816(s[jj*2  ], qh[kc][0], qh[kc][1], qh[kc][2], qh[kc][3], kh0, kh1);
                MMA16816(s[jj*2  ], qh[kc][0], qh[kc][1], qh[kc][2], qh[kc][3], kl0, kl1);
                MMA16816(s[jj*2  ], ql[kc][0], ql[kc][1], ql[kc][2], ql[kc][3], kh0, kh1);
                MMA16816(s[jj*2+1], qh[kc][0], qh[kc][1], qh[kc][2], qh[kc][3], kh2, kh3);
                MMA16816(s[jj*2+1], qh[kc][0], qh[kc][1], qh[kc][2], qh[kc][3], kl2, kl3);
                MMA16816(s[jj*2+1], ql[kc][0], ql[kc][1], ql[kc][2], ql[kc][3], kh2, kh3);
            }
        }

        #pragma unroll
        for (int j = 0; j < 8; j++)
            #pragma unroll
            for (int c = 0; c < 4; c++) s[j][c] *= 0.125f;

        if (kt * 64 + 63 > qt * 128 + w * 16) {
            #pragma unroll
            for (int j = 0; j < 8; j++) {
                int col = kt * 64 + j * 8 + qd * 2;
                if (col     > row0g) s[j][0] = -1e30f;
                if (col + 1 > row0g) s[j][1] = -1e30f;
                if (col     > row1g) s[j][2] = -1e30f;
                if (col + 1 > row1g) s[j][3] = -1e30f;
            }
        }

        float rm0 = -1e30f, rm1 = -1e30f;
        #pragma unroll
        for (int j = 0; j < 8; j++) {
            rm0 = fmaxf(rm0, fmaxf(s[j][0], s[j][1]));
            rm1 = fmaxf(rm1, fmaxf(s[j][2], s[j][3]));
        }
        rm0 = fmaxf(rm0, __shfl_xor_sync(0xffffffffu, rm0, 1));
        rm0 = fmaxf(rm0, __shfl_xor_sync(0xffffffffu, rm0, 2));
        rm1 = fmaxf(rm1, __shfl_xor_sync(0xffffffffu, rm1, 1));
        rm1 = fmaxf(rm1, __shfl_xor_sync(0xffffffffu, rm1, 2));
        float mn0 = fmaxf(mi0, rm0), mn1 = fmaxf(mi1, rm1);
        float al0 = __expf(mi0 - mn0), al1 = __expf(mi1 - mn1);
        mi0 = mn0; mi1 = mn1;
        float rs0 = 0.0f, rs1 = 0.0f;
        #pragma unroll
        for (int j = 0; j < 8; j++) {
            s[j][0] = __expf(s[j][0] - mn0);
            s[j][1] = __expf(s[j][1] - mn0);
            s[j][2] = __expf(s[j][2] - mn1);
            s[j][3] = __expf(s[j][3] - mn1);
            rs0 += s[j][0] + s[j][1];
            rs1 += s[j][2] + s[j][3];
        }
        rs0 += __shfl_xor_sync(0xffffffffu, rs0, 1);
        rs0 += __shfl_xor_sync(0xffffffffu, rs0, 2);
        rs1 += __shfl_xor_sync(0xffffffffu, rs1, 1);
        rs1 += __shfl_xor_sync(0xffffffffu, rs1, 2);
        li0 = li0 * al0 + rs0;
        li1 = li1 * al1 + rs1;

        #pragma unroll
        for (int j = 0; j < 8; j++) {
            o[j][0] *= al0; o[j][1] *= al0;
            o[j][2] *= al1; o[j][3] *= al1;
        }

        uint32_t pa[4][4];
        #pragma unroll
        for (int kc = 0; kc < 4; kc++) {
            pa[kc][0] = pack_bf2(s[2*kc  ][0], s[2*kc  ][1]);
            pa[kc][1] = pack_bf2(s[2*kc  ][2], s[2*kc  ][3]);
            pa[kc][2] = pack_bf2(s[2*kc+1][0], s[2*kc+1][1]);
            pa[kc][3] = pack_bf2(s[2*kc+1][2], s[2*kc+1][3]);
        }

        #pragma unroll
        for (int kc = 0; kc < 4; kc++) {
            #pragma unroll
            for (int jj = 0; jj < 4; jj++) {
                uint32_t addr_h = smem_u32(&Vh[(kc * 16 + (lane & 7) + ((lane >> 3) & 1) * 8) * FPITCH
                                               + (jj * 2 + (lane >> 4)) * 8]);
                uint32_t addr_l = smem_u32(&Vl[(kc * 16 + (lane & 7) + ((lane >> 3) & 1) * 8) * FPITCH
                                               + (jj * 2 + (lane >> 4)) * 8]);
                uint32_t vh0, vh1, vh2, vh3, vl0, vl1, vl2, vl3;
                LDSM_X4_T(vh0, vh1, vh2, vh3, addr_h);
                LDSM_X4_T(vl0, vl1, vl2, vl3, addr_l);
                MMA16816(o[jj*2  ], pa[kc][0], pa[kc][1], pa[kc][2], pa[kc][3], vh0, vh1);
                MMA16816(o[jj*2  ], pa[kc][0], pa[kc][1], pa[kc][2], pa[kc][3], vl0, vl1);
                MMA16816(o[jj*2+1], pa[kc][0], pa[kc][1], pa[kc][2], pa[kc][3], vh2, vh3);
                MMA16816(o[jj*2+1], pa[kc][0], pa[kc][1], pa[kc][2], pa[kc][3], vl2, vl3);
            }
        }
    }

    // ---- write z hi/lo [tok, h*64+dh] ----
    float inv0 = 1.0f / li0, inv1 = 1.0f / li1;
    size_t zoff = ((size_t)bb * SQ + (size_t)qt * FBM + w * 16) * DM + hh * DH;
    #pragma unroll
    for (int j = 0; j < 8; j++) {
        int col = j * 8 + qd * 2;
        float v00 = o[j][0] * inv0, v01 = o[j][1] * inv0;
        float v10 = o[j][2] * inv1, v11 = o[j][3] * inv1;
        bf16 h00,l00,h01,l01,h10,l10,h11,l11;
        split_val(v00,h00,l00); split_val(v01,h01,l01);
        split_val(v10,h10,l10); split_val(v11,h11,l11);
        __nv_bfloat162 p0h = {h00,h01}, p0l = {l00,l01};
        __nv_bfloat162 p1h = {h10,h11}, p1l = {l10,l11};
        *(__nv_bfloat162*)(zh + zoff + (size_t)gid * DM + col)       = p0h;
        *(__nv_bfloat162*)(zl + zoff + (size_t)gid * DM + col)       = p0l;
        *(__nv_bfloat162*)(zh + zoff + (size_t)(gid + 8) * DM + col) = p1h;
        *(__nv_bfloat162*)(zl + zoff + (size_t)(gid + 8) * DM + col) = p1l;
    }
}

// ---------------- host launcher ---------------------------------------------
template <typename T>
static T* sym_addr(const void* symbol) {
    void* p = nullptr;
    cudaGetSymbolAddress(&p, symbol);
    return (T*)p;
}

extern "C" void kernel_launch(void* const* d_in, const int* in_sizes, int n_in,
                              void* d_out, int out_size) {
    const float* resid_pre = (const float*)d_in[0];
    const float* ln1_w = (const float*)d_in[1];
    const float* ln1_b = (const float*)d_in[2];
    const float* W_Q   = (const float*)d_in[3];
    const float* b_Q   = (const float*)d_in[4];
    const float* W_K   = (const float*)d_in[5];
    const float* b_K   = (const float*)d_in[6];
    const float* W_V   = (const float*)d_in[7];
    const float* b_V   = (const float*)d_in[8];
    const float* W_O   = (const float*)d_in[9];
    const float* b_O   = (const float*)d_in[10];
    const float* ln2_w = (const float*)d_in[11];
    const float* ln2_b = (const float*)d_in[12];
    const float* W_in  = (const float*)d_in[13];
    const float* b_in  = (const float*)d_in[14];
    const float* W_out = (const float*)d_in[15];
    const float* b_out = (const float*)d_in[16];
    float* out = (float*)d_out;

    float* qb   = sym_addr<float>(g_q);
    float* kb   = sym_addr<float>(g_k);
    float* vb   = sym_addr<float>(g_v);
    float* rmid = sym_addr<float>(g_rmid);

    bf16* xln_h = sym_addr<bf16>(g_xln_h); bf16* xln_l = sym_addr<bf16>(g_xln_l);
    bf16* z_h   = sym_addr<bf16>(g_z_h);   bf16* z_l   = sym_addr<bf16>(g_z_l);
    bf16* h2_h  = sym_addr<bf16>(g_h2_h);  bf16* h2_l  = sym_addr<bf16>(g_h2_l);
    bf16* act_h = sym_addr<bf16>(g_act_h); bf16* act_l = sym_addr<bf16>(g_act_l);
    bf16* wq_h  = sym_addr<bf16>(g_wq_h);  bf16* wq_l  = sym_addr<bf16>(g_wq_l);
    bf16* wk_h  = sym_addr<bf16>(g_wk_h);  bf16* wk_l  = sym_addr<bf16>(g_wk_l);
    bf16* wv_h  = sym_addr<bf16>(g_wv_h);  bf16* wv_l  = sym_addr<bf16>(g_wv_l);
    bf16* wo_h  = sym_addr<bf16>(g_wo_h);  bf16* wo_l  = sym_addr<bf16>(g_wo_l);
    bf16* win_h = sym_addr<bf16>(g_win_h); bf16* win_l = sym_addr<bf16>(g_win_l);
    bf16* wout_h= sym_addr<bf16>(g_wout_h);bf16* wout_l= sym_addr<bf16>(g_wout_l);

    cudaFuncSetAttribute(hgemm_kernel<1>, cudaFuncAttributeMaxDynamicSharedMemorySize, HGEMM_SMEM);
    cudaFuncSetAttribute(hgemm_kernel<2>, cudaFuncAttributeMaxDynamicSharedMemorySize, HGEMM_SMEM);
    cudaFuncSetAttribute(hgemm_kernel<3>, cudaFuncAttributeMaxDynamicSharedMemorySize, HGEMM_SMEM);

    // 1. weight repack + split
    repack_kernel<<<(DM * DM) / 256, 256>>>(W_Q, W_K, W_V);
    split_kernel<<<(DM * DM) / 1024, 256>>>(W_O, wo_h, wo_l);
    split_kernel<<<(DM * DMLP) / 1024, 256>>>(W_in, win_h, win_l);
    split_kernel<<<(DMLP * DM) / 1024, 256>>>(W_out, wout_h, wout_l);

    // 2. LN1 -> bf16 hi/lo
    ln_kernel<<<NTOK, 256>>>(resid_pre, ln1_w, ln1_b, xln_h, xln_l);

    // 3. QKV projections (scatter to [b,h,s,dh] fp32)
    dim3 gq(DM / 128, NTOK / 128);
    hgemm_kernel<1><<<gq, 256, HGEMM_SMEM>>>(xln_h, xln_l, wq_h, wq_l, b_Q, nullptr, qb, nullptr, nullptr, NTOK, DM, DM);
    hgemm_kernel<1><<<gq, 256, HGEMM_SMEM>>>(xln_h, xln_l, wk_h, wk_l, b_K, nullptr, kb, nullptr, nullptr, NTOK, DM, DM);
    hgemm_kernel<1><<<gq, 256, HGEMM_SMEM>>>(xln_h, xln_l, wv_h, wv_l, b_V, nullptr, vb, nullptr, nullptr, NTOK, DM, DM);

    // 4. tensor-core flash attention -> z hi/lo
    const size_t fl_smem = (size_t)(2*FBM + 4*FBN) * FPITCH * sizeof(bf16); // 73728
    cudaFuncSetAttribute(flashmma_kernel,
                         cudaFuncAttributeMaxDynamicSharedMemorySize, (int)fl_smem);
    flashmma_kernel<<<dim3(SQ / FBM, BT * NH), 256, fl_smem>>>(qb, kb, vb, z_h, z_l);

    // 5. O-proj + residual -> resid_mid (fp32)
    hgemm_kernel<2><<<gq, 256, HGEMM_SMEM>>>(z_h, z_l, wo_h, wo_l, b_O, resid_pre, rmid, nullptr, nullptr, NTOK, DM, DM);

    // 6. LN2 -> bf16 hi/lo
    ln_kernel<<<NTOK, 256>>>(rmid, ln2_w, ln2_b, h2_h, h2_l);

    // 7. MLP in + ReLU -> act hi/lo
    dim3 gi(DMLP / 128, NTOK / 128);
    hgemm_kernel<3><<<gi, 256, HGEMM_SMEM>>>(h2_h, h2_l, win_h, win_l, b_in, nullptr, nullptr, act_h, act_l, NTOK, DMLP, DM);

    // 8. MLP out + bias + residual -> output (fp32)
    hgemm_kernel<2><<<gq, 256, HGEMM_SMEM>>>(act_h, act_l, wout_h, wout_l, b_out, rmid, out, nullptr, nullptr, NTOK, DM, DMLP);
}